// round 10
// baseline (speedup 1.0000x reference)
#include <cuda_runtime.h>
#include <cstddef>

static constexpr int N_UNITS = 16384;
static constexpr int K_TOP   = 655;
static constexpr int THREADS = 512;
static constexpr int NH      = 8;                        // level-0 histogram copies (2 warps each)
static constexpr int VPT4    = N_UNITS / (THREADS * 4);  // float4 vectors per thread = 8
static constexpr int KPT     = VPT4 * 4;                 // keys per thread = 32

__device__ float g_boost[N_UNITS];

__global__ void boost_kernel(const float* __restrict__ duty, int n, float targetDensity) {
    int i = blockIdx.x * blockDim.x + threadIdx.x;
    if (i < n) g_boost[i] = expf(targetDensity - duty[i]);
}

// Order-preserving float -> uint32 map (total order, larger float -> larger key).
__device__ __forceinline__ unsigned mono(float f) {
    unsigned u = __float_as_uint(f);
    return (u & 0x80000000u) ? ~u : (u | 0x80000000u);
}

// Warp-aggregated histogram add: lanes with equal 'bin' elect a leader that
// issues a single atomicAdd with the multiplicity. 'mask' = participating lanes.
__device__ __forceinline__ void hist_add(unsigned* h, unsigned bin, unsigned mask, int lane) {
    unsigned peers = __match_any_sync(mask, bin);
    if (lane == __ffs(peers) - 1)
        atomicAdd(&h[bin], (unsigned)__popc(peers));
}

__global__ __launch_bounds__(THREADS, 2) void kwinners_kernel(
    const float* __restrict__ x, float* __restrict__ out)
{
    __shared__ unsigned h0[NH][256];   // 8 KB: level-0 histograms, 2 warps per copy
    __shared__ unsigned hl[3][256];    // 3 KB: levels 1..3
    __shared__ unsigned warpTot[8];
    __shared__ unsigned sh_prefix;
    __shared__ int sh_k;

    const int tid  = threadIdx.x;
    const int wid  = tid >> 5;
    const int lane = tid & 31;
    const size_t rowOff = (size_t)blockIdx.x * N_UNITS;
    const float4* __restrict__ xr = (const float4*)(x + rowOff);
    const float4* __restrict__ br = (const float4*)g_boost;

    // ---- Clear all histogram buffers once, up front ----
    #pragma unroll
    for (int j = tid; j < (NH + 3) * 256; j += THREADS) (&h0[0][0])[j] = 0u;
    if (tid == 0) { sh_prefix = 0u; sh_k = K_TOP; }

    // ---- Load row, apply boost; keys stay in registers (loads front-batch) ----
    unsigned key[KPT];
    #pragma unroll
    for (int i = 0; i < VPT4; i++) {
        int v = tid + THREADS * i;
        float4 xv = __ldcs(&xr[v]);     // read-once: evict-first
        float4 bv = __ldg(&br[v]);      // reused across CTAs: keep cached
        key[4*i + 0] = mono(xv.x * bv.x);
        key[4*i + 1] = mono(xv.y * bv.y);
        key[4*i + 2] = mono(xv.z * bv.z);
        key[4*i + 3] = mono(xv.w * bv.w);
    }
    __syncthreads();   // clears complete (overlapped with loads)

    // ---- Level-0 histogram: warp-aggregated atomics ----
    {
        unsigned* h = h0[wid & (NH - 1)];
        #pragma unroll
        for (int j = 0; j < KPT; j++)
            hist_add(h, key[j] >> 24, 0xFFFFFFFFu, lane);
    }
    __syncthreads();

    unsigned decided = 0;

    #pragma unroll 1
    for (int level = 0; level < 4; level++) {
        const int shift = 24 - 8 * level;
        const unsigned prefix = sh_prefix;
        const int k = sh_k;

        if (level > 0) {
            // sparse, aggregated atomics: only keys matching the decided prefix
            unsigned* hb = hl[level - 1];
            #pragma unroll
            for (int j = 0; j < KPT; j++) {
                unsigned kk = key[j];
                bool pred = (kk & decided) == prefix;
                unsigned m = __ballot_sync(0xFFFFFFFFu, pred);
                if (pred)
                    hist_add(hb, (kk >> shift) & 0xFFu, m, lane);
            }
            __syncthreads();
        }

        // Parallel suffix-sum over 256 bins + pivot decision.
        unsigned v = 0, s = 0;
        if (tid < 256) {
            if (level == 0) {
                #pragma unroll
                for (int c = 0; c < NH; c++) v += h0[c][tid];
            } else {
                v = hl[level - 1][tid];
            }
            s = v;
            #pragma unroll
            for (int off = 1; off < 32; off <<= 1) {
                unsigned t = __shfl_down_sync(0xFFFFFFFFu, s, off);
                if (lane + off < 32) s += t;
            }
            if (lane == 0) warpTot[tid >> 5] = s;
        }
        __syncthreads();
        if (tid < 256) {
            unsigned above = 0;
            #pragma unroll
            for (int w = 0; w < 8; w++)
                if (w > (tid >> 5)) above += warpTot[w];
            unsigned ssum = s + above;                 // count of keys >= start of bin 'tid'
            if (ssum >= (unsigned)k && (ssum - v) < (unsigned)k) {
                sh_prefix = prefix | ((unsigned)tid << shift);
                sh_k = k - (int)(ssum - v);
            }
        }
        decided |= 0xFFu << shift;
        __syncthreads();
    }

    const unsigned T = sh_prefix;   // exact key of the K-th largest element

    // ---- Write binary mask straight from registers ----
    float4* __restrict__ orow = (float4*)(out + rowOff);
    #pragma unroll
    for (int i = 0; i < VPT4; i++) {
        int v = tid + THREADS * i;
        float4 m;
        m.x = (key[4*i + 0] >= T) ? 1.0f : 0.0f;
        m.y = (key[4*i + 1] >= T) ? 1.0f : 0.0f;
        m.z = (key[4*i + 2] >= T) ? 1.0f : 0.0f;
        m.w = (key[4*i + 3] >= T) ? 1.0f : 0.0f;
        __stcs(&orow[v], m);
    }
}

extern "C" void kernel_launch(void* const* d_in, const int* in_sizes, int n_in,
                              void* d_out, int out_size) {
    const float* x    = (const float*)d_in[0];   // (B, N) float32
    const float* duty = (const float*)d_in[1];   // (N,)   float32
    float* out        = (float*)d_out;

    const int n = in_sizes[1];                   // 16384
    const int B = in_sizes[0] / n;               // 4096
    const float targetDensity = (float)K_TOP / (float)n;

    boost_kernel<<<(n + 255) / 256, 256>>>(duty, n, targetDensity);
    kwinners_kernel<<<B, THREADS>>>(x, out);
}

// round 11
// speedup vs baseline: 2.8685x; 2.8685x over previous
#include <cuda_runtime.h>
#include <cstddef>

static constexpr int N_UNITS = 16384;
static constexpr int K_TOP   = 655;
static constexpr int THREADS = 512;
static constexpr int NH      = 8;                        // sampled-histogram copies (2 warps each)
static constexpr int VPT4    = N_UNITS / (THREADS * 4);  // float4 vectors per thread = 8
static constexpr int KPT     = VPT4 * 4;                 // keys per thread = 32
static constexpr int SAMPLE_STRIDE = 8;                  // histogram every 8th key
static constexpr int K_SAMPLE = (K_TOP + SAMPLE_STRIDE - 1) / SAMPLE_STRIDE;  // 82

__device__ float g_boost[N_UNITS];

__global__ void boost_kernel(const float* __restrict__ duty, int n, float targetDensity) {
    int i = blockIdx.x * blockDim.x + threadIdx.x;
    if (i < n) g_boost[i] = expf(targetDensity - duty[i]);
}

// Order-preserving float -> uint32 map (total order, larger float -> larger key).
__device__ __forceinline__ unsigned mono(float f) {
    unsigned u = __float_as_uint(f);
    return (u & 0x80000000u) ? ~u : (u | 0x80000000u);
}

__global__ __launch_bounds__(THREADS, 2) void kwinners_kernel(
    const float* __restrict__ x, float* __restrict__ out)
{
    __shared__ unsigned h0[NH][256];   // 8 KB: sampled level-0 histograms
    __shared__ unsigned hl[3][256];    // 3 KB: levels 1..3 (full, sparse)
    __shared__ unsigned warpTot[8];
    __shared__ unsigned wt0[16], wt1[16];
    __shared__ unsigned sh_prefix;
    __shared__ int sh_k;
    __shared__ int sh_b;
    __shared__ int sh_done;

    const int tid  = threadIdx.x;
    const int wid  = tid >> 5;
    const int lane = tid & 31;
    const size_t rowOff = (size_t)blockIdx.x * N_UNITS;
    const float4* __restrict__ xr = (const float4*)(x + rowOff);
    const float4* __restrict__ br = (const float4*)g_boost;

    // ---- Clear all histogram buffers once, up front (overlaps with loads) ----
    #pragma unroll
    for (int j = tid; j < (NH + 3) * 256; j += THREADS) (&h0[0][0])[j] = 0u;
    if (tid == 0) sh_prefix = 0u;

    // ---- Load row, apply boost; keys stay in registers (loads front-batched) ----
    unsigned key[KPT];
    #pragma unroll
    for (int i = 0; i < VPT4; i++) {
        int v = tid + THREADS * i;
        float4 xv = __ldcs(&xr[v]);     // read-once: evict-first
        float4 bv = __ldg(&br[v]);      // reused across CTAs: keep cached
        key[4*i + 0] = mono(xv.x * bv.x);
        key[4*i + 1] = mono(xv.y * bv.y);
        key[4*i + 2] = mono(xv.z * bv.z);
        key[4*i + 3] = mono(xv.w * bv.w);
    }
    __syncthreads();

    // ---- Sampled level-0 histogram: every 8th key (4 atomics/thread) ----
    {
        unsigned* h = h0[wid & (NH - 1)];
        #pragma unroll
        for (int j = 0; j < KPT; j += SAMPLE_STRIDE)
            atomicAdd(&h[key[j] >> 24], 1u);
    }
    __syncthreads();

    // ---- Suffix-scan sampled histogram -> guess byte b_hat ----
    {
        unsigned v = 0, s = 0;
        if (tid < 256) {
            #pragma unroll
            for (int c = 0; c < NH; c++) v += h0[c][tid];
            s = v;
            #pragma unroll
            for (int off = 1; off < 32; off <<= 1) {
                unsigned t = __shfl_down_sync(0xFFFFFFFFu, s, off);
                if (lane + off < 32) s += t;
            }
            if (lane == 0) warpTot[tid >> 5] = s;
        }
        __syncthreads();
        if (tid < 256) {
            unsigned above = 0;
            #pragma unroll
            for (int w = 0; w < 8; w++)
                if (w > (tid >> 5)) above += warpTot[w];
            unsigned ssum = s + above;
            if (ssum >= (unsigned)K_SAMPLE && (ssum - v) < (unsigned)K_SAMPLE)
                sh_b = tid;
        }
        __syncthreads();
    }

    // ---- Exact fixup walk: find b* with f(b*+1) < K <= f(b*), f(b)=#{topbyte>=b} ----
    {
        int b = sh_b;
        #pragma unroll 1
        for (int iter = 0; iter < 256; iter++) {
            unsigned c0 = 0, c1 = 0;
            const unsigned ub = (unsigned)b;
            #pragma unroll
            for (int j = 0; j < KPT; j++) {
                unsigned tb = key[j] >> 24;
                c0 += (tb >= ub);
                c1 += (tb >  ub);
            }
            #pragma unroll
            for (int off = 16; off > 0; off >>= 1) {
                c0 += __shfl_down_sync(0xFFFFFFFFu, c0, off);
                c1 += __shfl_down_sync(0xFFFFFFFFu, c1, off);
            }
            if (lane == 0) { wt0[wid] = c0; wt1[wid] = c1; }
            __syncthreads();
            if (tid == 0) {
                unsigned f0 = 0, f1 = 0;
                #pragma unroll
                for (int w = 0; w < 16; w++) { f0 += wt0[w]; f1 += wt1[w]; }
                if (f0 < (unsigned)K_TOP) { sh_b = b - 1; sh_done = 0; }
                else if (f1 >= (unsigned)K_TOP) { sh_b = b + 1; sh_done = 0; }
                else {
                    sh_prefix = (unsigned)b << 24;
                    sh_k = K_TOP - (int)f1;
                    sh_done = 1;
                }
            }
            __syncthreads();
            if (sh_done) break;
            b = sh_b;
        }
    }

    unsigned decided = 0xFF000000u;

    // ---- Levels 1..3: sparse radix refine among keys matching the prefix ----
    #pragma unroll 1
    for (int level = 1; level < 4; level++) {
        const int shift = 24 - 8 * level;
        const unsigned prefix = sh_prefix;
        const int k = sh_k;

        unsigned* hb = hl[level - 1];
        #pragma unroll
        for (int j = 0; j < KPT; j++) {
            unsigned kk = key[j];
            if ((kk & decided) == prefix)
                atomicAdd(&hb[(kk >> shift) & 0xFFu], 1u);
        }
        __syncthreads();

        unsigned v = 0, s = 0;
        if (tid < 256) {
            v = hb[tid];
            s = v;
            #pragma unroll
            for (int off = 1; off < 32; off <<= 1) {
                unsigned t = __shfl_down_sync(0xFFFFFFFFu, s, off);
                if (lane + off < 32) s += t;
            }
            if (lane == 0) warpTot[tid >> 5] = s;
        }
        __syncthreads();
        if (tid < 256) {
            unsigned above = 0;
            #pragma unroll
            for (int w = 0; w < 8; w++)
                if (w > (tid >> 5)) above += warpTot[w];
            unsigned ssum = s + above;                 // count of keys >= start of bin 'tid'
            if (ssum >= (unsigned)k && (ssum - v) < (unsigned)k) {
                sh_prefix = prefix | ((unsigned)tid << shift);
                sh_k = k - (int)(ssum - v);
            }
        }
        decided |= 0xFFu << shift;
        __syncthreads();
    }

    const unsigned T = sh_prefix;   // exact key of the K-th largest element

    // ---- Write binary mask straight from registers ----
    float4* __restrict__ orow = (float4*)(out + rowOff);
    #pragma unroll
    for (int i = 0; i < VPT4; i++) {
        int v = tid + THREADS * i;
        float4 m;
        m.x = (key[4*i + 0] >= T) ? 1.0f : 0.0f;
        m.y = (key[4*i + 1] >= T) ? 1.0f : 0.0f;
        m.z = (key[4*i + 2] >= T) ? 1.0f : 0.0f;
        m.w = (key[4*i + 3] >= T) ? 1.0f : 0.0f;
        __stcs(&orow[v], m);
    }
}

extern "C" void kernel_launch(void* const* d_in, const int* in_sizes, int n_in,
                              void* d_out, int out_size) {
    const float* x    = (const float*)d_in[0];   // (B, N) float32
    const float* duty = (const float*)d_in[1];   // (N,)   float32
    float* out        = (float*)d_out;

    const int n = in_sizes[1];                   // 16384
    const int B = in_sizes[0] / n;               // 4096
    const float targetDensity = (float)K_TOP / (float)n;

    boost_kernel<<<(n + 255) / 256, 256>>>(duty, n, targetDensity);
    kwinners_kernel<<<B, THREADS>>>(x, out);
}